// round 9
// baseline (speedup 1.0000x reference)
#include <cuda_runtime.h>
#include <math.h>

#define T_STEPS 2048
#define BATCH   16
#define DDIM    1024
#define NPROJ   448           // 384 (kv) + 64 (q)
#define NOUT    (T_STEPS*BATCH*64)
#define MSIZE   (3*BATCH*64*64)
#define NSCAN   16
#define NCTA    148
#define NGEMM   (NCTA-NSCAN)
#define NRB     512           // row blocks of 64 proj rows (= 4 timesteps)
#define NTILES  (NRB*7)

__device__ float g_proj[(size_t)T_STEPS * BATCH * NPROJ];
__device__ int   g_cnt[NRB];

typedef unsigned long long ull;

__device__ __forceinline__ ull pk2(float lo, float hi) {
    ull r; asm("mov.b64 %0,{%1,%2};" : "=l"(r) : "f"(lo), "f"(hi)); return r;
}
__device__ __forceinline__ void upk2(ull v, float& a, float& b) {
    asm("mov.b64 {%0,%1},%2;" : "=f"(a), "=f"(b) : "l"(v));
}
__device__ __forceinline__ ull f2fma(ull a, ull b, ull c) {
    ull d; asm("fma.rn.f32x2 %0,%1,%2,%3;" : "=l"(d) : "l"(a), "l"(b), "l"(c)); return d;
}
__device__ __forceinline__ ull f2mul(ull a, ull b) {
    ull d; asm("mul.rn.f32x2 %0,%1,%2;" : "=l"(d) : "l"(a), "l"(b)); return d;
}
__device__ __forceinline__ int ldacq(const int* p) {
    int v; asm volatile("ld.acquire.gpu.global.b32 %0,[%1];" : "=r"(v) : "l"(p) : "memory"); return v;
}
__device__ __forceinline__ void redrel(int* p) {
    asm volatile("red.release.gpu.global.add.s32 [%0],1;" :: "l"(p) : "memory");
}
__device__ __forceinline__ unsigned smem_u32(const void* p) {
    unsigned a;
    asm("{.reg .u64 t; cvta.to.shared.u64 t,%1; cvt.u32.u64 %0,t;}" : "=r"(a) : "l"(p));
    return a;
}
__device__ __forceinline__ void cp16(unsigned dst, const void* src) {
    asm volatile("cp.async.cg.shared.global [%0],[%1],16;" :: "r"(dst), "l"(src) : "memory");
}
__device__ __forceinline__ void cp_commit() {
    asm volatile("cp.async.commit_group;" ::: "memory");
}
__device__ __forceinline__ void cp_wait1() {
    asm volatile("cp.async.wait_group 1;" ::: "memory");
}
__device__ __forceinline__ float sigm(float x) {
    return __fdividef(1.0f, 1.0f + __expf(-x));
}

__global__ void zero_cnt() { if (threadIdx.x < NRB) g_cnt[threadIdx.x] = 0; }

struct GemmS { float Xs[16][64]; float Ws[16][64]; };
struct ScanS {
    float raw[8][NPROJ];       // 8-deep ring of projection rows
    float kn[4][3][64];        // normalized k, 4-deep
    float cgkn[4][3][128];     // {cg[2p],cg[2p+1],kn[2p],kn[2p+1]}, 4-deep
    float rgdl[2][3][128];     // {rg[2p],rg[2p+1],dl[2p],dl[2p+1]}, 2-deep
};

// ===========================================================================
// GEMM producer body (256 compute threads, 4x4 micro-tile — proven).
// ===========================================================================
__device__ __forceinline__ void gemm_body(
    GemmS& G, int tid, int bx,
    const float* __restrict__ X, const float* __restrict__ Wkv,
    const float* __restrict__ Wq)
{
    const int tx = tid & 15;
    const int ty = tid >> 4;          // valid for tid<256
    const int lr = tid >> 2;
    const int lc = (tid & 3) * 4;

    for (int tt = bx - NSCAN; tt < NTILES; tt += NGEMM) {
        const int rb = tt / 7, cb = tt % 7;
        const int bm = rb * 64, bn = cb * 64;

        float acc[4][4];
#pragma unroll
        for (int a = 0; a < 4; a++)
#pragma unroll
            for (int c = 0; c < 4; c++) acc[a][c] = 0.f;

        const float* xrow = X + (size_t)(bm + lr) * DDIM + lc;
        const int wr = bn + lr;
        const float* wrow = (wr < 384 ? Wkv + (size_t)wr * DDIM
                                      : Wq + (size_t)(wr - 384) * DDIM) + lc;

        for (int k0 = 0; k0 < DDIM; k0 += 16) {
            if (tid < 256) {
                float4 xv = *(const float4*)(xrow + k0);
                float4 wv = *(const float4*)(wrow + k0);
                G.Xs[lc + 0][lr] = xv.x; G.Xs[lc + 1][lr] = xv.y;
                G.Xs[lc + 2][lr] = xv.z; G.Xs[lc + 3][lr] = xv.w;
                G.Ws[lc + 0][lr] = wv.x; G.Ws[lc + 1][lr] = wv.y;
                G.Ws[lc + 2][lr] = wv.z; G.Ws[lc + 3][lr] = wv.w;
            }
            __syncthreads();
            if (tid < 256) {
#pragma unroll
                for (int kk = 0; kk < 16; kk++) {
                    float4 xr4 = *(const float4*)&G.Xs[kk][ty * 4];
                    float4 wr4 = *(const float4*)&G.Ws[kk][tx * 4];
                    float xa[4] = {xr4.x, xr4.y, xr4.z, xr4.w};
                    float wb[4] = {wr4.x, wr4.y, wr4.z, wr4.w};
#pragma unroll
                    for (int a = 0; a < 4; a++)
#pragma unroll
                        for (int c = 0; c < 4; c++)
                            acc[a][c] = fmaf(xa[a], wb[c], acc[a][c]);
                }
            }
            __syncthreads();
        }
        if (tid < 256) {
#pragma unroll
            for (int a = 0; a < 4; a++) {
                float4 o = {acc[a][0], acc[a][1], acc[a][2], acc[a][3]};
                *(float4*)&g_proj[(size_t)(bm + ty * 4 + a) * NPROJ + bn + tx * 4] = o;
            }
        }
        __syncthreads();
        if (tid == 0) redrel(&g_cnt[rb]);
    }
}

// ===========================================================================
// Fused kernel, 384 threads. Scan state kept FACTORED:
//   M  = sr_i * N      (sr accumulates row gates;  N in Mr2 regs)
//   M^T= sc_i * NT     (sc accumulates col gates; NT in MTr2 regs)
// Update per step: N[j] = N[j]*cg[j] + (d_i/sr_new)*kn[j]   (2 f2 ops)
//                  NT[j]= NT[j]*rg[j] + (kn_i/sc_new)*d[j]  (2 f2 ops)
// Dots re-scale by sr / sc after the warp reduction. Scales are clamped
// (>=1e-30) and folded back into N/NT when they drop below 1e-12.
// ===========================================================================
__global__ __launch_bounds__(384, 1) void fused384(
    const float* __restrict__ X,
    const float* __restrict__ Wkv,
    const float* __restrict__ Wq,
    const float* __restrict__ Mi,
    const float* __restrict__ Bg,
    float* __restrict__ out,
    int write_M)
{
    __shared__ __align__(16) union { GemmS g; ScanS s; } sm;
    const int tid = threadIdx.x;

    if (blockIdx.x >= NSCAN) {
        gemm_body(sm.g, tid, (int)blockIdx.x, X, Wkv, Wq);
        return;
    }

    const int b    = blockIdx.x;
    const int g    = tid >> 7;
    const int r    = tid & 127;
    const int i    = r >> 1;
    const int h    = tid & 1;
    const int gm1  = (g + 2) % 3;
    const int wid  = tid >> 5, lane = tid & 31;
    ScanS& S = sm.s;

    ull Mr2[16], MTr2[16];
    {
        const float* M0 = Mi + ((size_t)(g * BATCH + b)) * 4096;
#pragma unroll
        for (int j = 0; j < 16; j++) {
            float2 a = *(const float2*)&M0[i * 64 + 32 * h + 2 * j];
            Mr2[j]  = pk2(a.x, a.y);
            MTr2[j] = pk2(M0[(32 * h + 2 * j) * 64 + i],
                          M0[(32 * h + 2 * j + 1) * 64 + i]);
        }
    }
    const float bgm = Bg[gm1 * 64 + i];
    float sr = 1.0f, sc = 1.0f;          // factored row/col gate scales

    const bool pf   = (tid >= 128 && tid < 240);  // warps 4-7 (g=1): prefetch
    const int  pidx = tid - 128;
    const bool knw  = (wid >= 8 && wid < 11);     // warps 8-10 (g=2): kn-next
    const int  kw   = wid - 8;
    int verified = 0;

    if (pf) {
        while (ldacq(&g_cnt[0]) < 7) __nanosleep(64);
#pragma unroll
        for (int rr = 0; rr < 3; rr++) {
            cp16(smem_u32(&S.raw[rr][pidx * 4]),
                 g_proj + (size_t)(rr * BATCH + b) * NPROJ + pidx * 4);
            cp_commit();
        }
        cp16(smem_u32(&S.raw[3][pidx * 4]),
             g_proj + (size_t)(3 * BATCH + b) * NPROJ + pidx * 4);
        cp_commit();
        cp_wait1();    // rows 0..2 complete, row 3 pending
    }
    __syncthreads();
    if (knw) {         // kn for row 0
        float a0 = S.raw[0][kw * 128 + lane];
        float a1 = S.raw[0][kw * 128 + 32 + lane];
        float ssq = a0 * a0 + a1 * a1;
#pragma unroll
        for (int o = 16; o; o >>= 1) ssq += __shfl_xor_sync(0xffffffffu, ssq, o);
        float inv = __fdividef(1.0f, sqrtf(ssq) + 1e-6f);
        float k0 = a0 * inv, k1 = a1 * inv;
        S.kn[0][kw][lane]      = k0;
        S.kn[0][kw][lane + 32] = k1;
        S.cgkn[0][kw][4 * (lane >> 1) + 2 + (lane & 1)]        = k0;
        S.cgkn[0][kw][4 * ((lane + 32) >> 1) + 2 + (lane & 1)] = k1;
    }
    __syncthreads();

    for (int t = 0; t < T_STEPS; t++) {
        const int cur = t & 7, b4 = t & 3, b2 = t & 1;
        const int nb4 = (t + 1) & 3;

        // ---- region A: dots (on N/NT) + gates (re-scaled by sr/sc) ----
        ull rp = 0ull, ap = 0ull, cp = 0ull;
        {
            const ulonglong2* kg = (const ulonglong2*)(S.kn[b4][g]   + 32 * h);
            const ulonglong2* km = (const ulonglong2*)(S.kn[b4][gm1] + 32 * h);
#pragma unroll
            for (int j4 = 0; j4 < 8; j4++) {
                ulonglong2 kv  = kg[j4];
                ulonglong2 kmv = km[j4];
                rp = f2fma(Mr2[2 * j4],     kv.x,  rp);
                rp = f2fma(Mr2[2 * j4 + 1], kv.y,  rp);
                ap = f2fma(Mr2[2 * j4],     kmv.x, ap);
                ap = f2fma(Mr2[2 * j4 + 1], kmv.y, ap);
                cp = f2fma(MTr2[2 * j4],     kmv.x, cp);
                cp = f2fma(MTr2[2 * j4 + 1], kmv.y, cp);
            }
        }
        float rlo, rhi, alo, ahi, clo, chi;
        upk2(rp, rlo, rhi); upk2(ap, alo, ahi); upk2(cp, clo, chi);
        float rpart = rlo + rhi, apart = alo + ahi, cpart = clo + chi;
        rpart += __shfl_xor_sync(0xffffffffu, rpart, 1);
        apart += __shfl_xor_sync(0xffffffffu, apart, 1);
        cpart += __shfl_xor_sync(0xffffffffu, cpart, 1);
        const int pi = 4 * (i >> 1);
        if (!h) {
            S.rgdl[b2][gm1][pi + (i & 1)]     = sigm(fmaf(apart, sr, bgm));
            S.rgdl[b2][g]  [pi + 2 + (i & 1)] =
                fmaf(rpart, -sr, S.raw[cur][g * 128 + 64 + i]);   // v - sr*(N·k)
        } else {
            S.cgkn[b4][gm1][pi + (i & 1)]     = sigm(fmaf(cpart, sc, bgm));
        }

        // ---- kn for row t+1 (warps 8-10) ----
        if (knw && t + 1 < T_STEPS) {
            float a0 = S.raw[(t + 1) & 7][kw * 128 + lane];
            float a1 = S.raw[(t + 1) & 7][kw * 128 + 32 + lane];
            float ssq = a0 * a0 + a1 * a1;
#pragma unroll
            for (int o = 16; o; o >>= 1) ssq += __shfl_xor_sync(0xffffffffu, ssq, o);
            float inv = __fdividef(1.0f, sqrtf(ssq) + 1e-6f);
            float k0 = a0 * inv, k1 = a1 * inv;
            S.kn[nb4][kw][lane]      = k0;
            S.kn[nb4][kw][lane + 32] = k1;
            S.cgkn[nb4][kw][4 * (lane >> 1) + 2 + (lane & 1)]        = k0;
            S.cgkn[nb4][kw][4 * ((lane + 32) >> 1) + 2 + (lane & 1)] = k1;
        }

        // ---- prefetch row t+4 (warps 4-7, flag poll cached) ----
        if (pf) {
            const int t4 = t + 4;
            if (t4 < T_STEPS) {
                const int r4 = t4 * BATCH + b;
                const int rb4 = r4 >> 6;
                if (rb4 > verified) {
                    while (ldacq(&g_cnt[rb4]) < 7) __nanosleep(64);
                    verified = rb4;
                }
                cp16(smem_u32(&S.raw[t4 & 7][pidx * 4]),
                     g_proj + (size_t)r4 * NPROJ + pidx * 4);
            }
            cp_commit();
            cp_wait1();
        }
        __syncthreads();

        // ---- region B: factored update (2 f2 ops per row-pair) + output ----
        const float cg_i = S.cgkn[b4][g][pi + (i & 1)];
        const float kn_i = S.cgkn[b4][g][pi + 2 + (i & 1)];
        const float rg_i = S.rgdl[b2][g][pi + (i & 1)];
        const float d_i  = S.rgdl[b2][g][pi + 2 + (i & 1)];
        sr = fmaxf(sr * rg_i, 1e-30f);
        sc = fmaxf(sc * cg_i, 1e-30f);
        const float dp = __fdividef(d_i,  sr);
        const float kp = __fdividef(kn_i, sc);
        const ull dpd = pk2(dp, dp), kpd = pk2(kp, kp);
        {
            const ulonglong2* ck = (const ulonglong2*)(S.cgkn[b4][g] + 64 * h);
            const ulonglong2* rd = (const ulonglong2*)(S.rgdl[b2][g] + 64 * h);
#pragma unroll
            for (int j = 0; j < 16; j++) {
                ulonglong2 a  = ck[j];   // {cg pair, kn pair}
                ulonglong2 bq = rd[j];   // {rg pair, dl pair}
                Mr2[j]  = f2fma(Mr2[j],  a.x,  f2mul(a.y,  dpd));
                MTr2[j] = f2fma(MTr2[j], bq.x, f2mul(bq.y, kpd));
            }
        }
        // fold scales back into N/NT when tiny (rare, predicated)
        if (sr < 1e-12f) {
            const ull sp = pk2(sr, sr);
#pragma unroll
            for (int j = 0; j < 16; j++) Mr2[j] = f2mul(Mr2[j], sp);
            sr = 1.0f;
        }
        if (sc < 1e-12f) {
            const ull cp2 = pk2(sc, sc);
#pragma unroll
            for (int j = 0; j < 16; j++) MTr2[j] = f2mul(MTr2[j], cp2);
            sc = 1.0f;
        }

        if (!g) {
            ull sq = 0ull;
            const ulonglong2* q2 = (const ulonglong2*)(S.raw[cur] + 384 + 32 * h);
#pragma unroll
            for (int j4 = 0; j4 < 8; j4++) {
                ulonglong2 q = q2[j4];
                sq = f2fma(Mr2[2 * j4],     q.x, sq);
                sq = f2fma(Mr2[2 * j4 + 1], q.y, sq);
            }
            float slo, shi; upk2(sq, slo, shi);
            float sv = slo + shi;
            sv += __shfl_xor_sync(0xffffffffu, sv, 1);
            sv *= sr;                               // M_new = sr * N_new
            if (!h) out[((size_t)t * BATCH + b) * 64 + i] = sv * sigm(sv);
        }
    }

    if (write_M) {
        float* Mo = out + NOUT + ((size_t)(g * BATCH + b)) * 4096
                    + (size_t)i * 64 + 32 * h;
#pragma unroll
        for (int j = 0; j < 16; j++) {
            float a, c; upk2(Mr2[j], a, c);
            Mo[2 * j] = sr * a; Mo[2 * j + 1] = sr * c;
        }
    }
}

// ---------------------------------------------------------------------------
extern "C" void kernel_launch(void* const* d_in, const int* in_sizes, int n_in,
                              void* d_out, int out_size)
{
    const float *x = nullptr, *Mi = nullptr, *Wkv = nullptr,
                *Wq = nullptr, *Bg = nullptr;
    for (int idx = 0; idx < n_in; idx++) {
        switch (in_sizes[idx]) {
            case 33554432: x   = (const float*)d_in[idx]; break;
            case 196608:   Mi  = (const float*)d_in[idx]; break;
            case 393216:   Wkv = (const float*)d_in[idx]; break;
            case 65536:    Wq  = (const float*)d_in[idx]; break;
            case 192:      Bg  = (const float*)d_in[idx]; break;
        }
    }
    if (!x || !Mi || !Wkv || !Wq || !Bg) {
        x   = (const float*)d_in[0];
        Mi  = (const float*)d_in[1];
        Wkv = (const float*)d_in[2];
        Wq  = (const float*)d_in[3];
        Bg  = (const float*)d_in[4];
    }

    const int write_M = (out_size >= NOUT + MSIZE) ? 1 : 0;

    zero_cnt<<<1, 512>>>();
    fused384<<<NCTA, 384>>>(x, Wkv, Wq, Mi, Bg, (float*)d_out, write_M);
}

// round 10
// speedup vs baseline: 1.1115x; 1.1115x over previous
#include <cuda_runtime.h>
#include <math.h>

#define T_STEPS 2048
#define BATCH   16
#define DDIM    1024
#define NPROJ   448           // 384 (kv) + 64 (q)
#define NOUT    (T_STEPS*BATCH*64)
#define MSIZE   (3*BATCH*64*64)
#define NSCAN   16
#define NCTA    148
#define NGEMM   (NCTA-NSCAN)
#define NRB     512           // row blocks of 64 proj rows (= 4 timesteps)
#define NTILES  (NRB*7)

__device__ float g_proj[(size_t)T_STEPS * BATCH * NPROJ];
__device__ int   g_cnt[NRB];

typedef unsigned long long ull;

__device__ __forceinline__ ull pk2(float lo, float hi) {
    ull r; asm("mov.b64 %0,{%1,%2};" : "=l"(r) : "f"(lo), "f"(hi)); return r;
}
__device__ __forceinline__ void upk2(ull v, float& a, float& b) {
    asm("mov.b64 {%0,%1},%2;" : "=f"(a), "=f"(b) : "l"(v));
}
__device__ __forceinline__ ull f2fma(ull a, ull b, ull c) {
    ull d; asm("fma.rn.f32x2 %0,%1,%2,%3;" : "=l"(d) : "l"(a), "l"(b), "l"(c)); return d;
}
__device__ __forceinline__ ull f2mul(ull a, ull b) {
    ull d; asm("mul.rn.f32x2 %0,%1,%2;" : "=l"(d) : "l"(a), "l"(b)); return d;
}
__device__ __forceinline__ int ldacq(const int* p) {
    int v; asm volatile("ld.acquire.gpu.global.b32 %0,[%1];" : "=r"(v) : "l"(p) : "memory"); return v;
}
__device__ __forceinline__ void redrel(int* p) {
    asm volatile("red.release.gpu.global.add.s32 [%0],1;" :: "l"(p) : "memory");
}
__device__ __forceinline__ unsigned smem_u32(const void* p) {
    unsigned a;
    asm("{.reg .u64 t; cvta.to.shared.u64 t,%1; cvt.u32.u64 %0,t;}" : "=r"(a) : "l"(p));
    return a;
}
__device__ __forceinline__ void cp16(unsigned dst, const void* src) {
    asm volatile("cp.async.cg.shared.global [%0],[%1],16;" :: "r"(dst), "l"(src) : "memory");
}
__device__ __forceinline__ void cp_commit() {
    asm volatile("cp.async.commit_group;" ::: "memory");
}
__device__ __forceinline__ void cp_wait1() {
    asm volatile("cp.async.wait_group 1;" ::: "memory");
}
__device__ __forceinline__ float sigm(float x) {
    return __fdividef(1.0f, 1.0f + __expf(-x));
}

__global__ void zero_cnt() { if (threadIdx.x < NRB) g_cnt[threadIdx.x] = 0; }

struct GemmS { float Xs[16][64]; float Ws[16][64]; };
struct ScanA {                 // R8 layout
    float raw[8][NPROJ];
    float kn[4][3][64];
    float cgkn[4][3][128];     // {cg[2p],cg[2p+1],kn[2p],kn[2p+1]}
    float rgdl[2][3][128];     // {rg[2p],rg[2p+1],dl[2p],dl[2p+1]}
};
struct ScanB {                 // kn-in-regs layout
    float raw[8][NPROJ];
    float kn[4][3][64];
    float cg[4][3][64];        // plain column gates
    float rgdl[2][3][128];     // {rg[2p],rg[2p+1],dl[2p],dl[2p+1]}
};

// ===========================================================================
// GEMM producer body (256 compute threads, 4x4 micro-tile — proven).
// ===========================================================================
__device__ __forceinline__ void gemm_body(
    GemmS& G, int tid, int bx,
    const float* __restrict__ X, const float* __restrict__ Wkv,
    const float* __restrict__ Wq)
{
    const int tx = tid & 15;
    const int ty = tid >> 4;
    const int lr = tid >> 2;
    const int lc = (tid & 3) * 4;

    for (int tt = bx - NSCAN; tt < NTILES; tt += NGEMM) {
        const int rb = tt / 7, cb = tt % 7;
        const int bm = rb * 64, bn = cb * 64;

        float acc[4][4];
#pragma unroll
        for (int a = 0; a < 4; a++)
#pragma unroll
            for (int c = 0; c < 4; c++) acc[a][c] = 0.f;

        const float* xrow = X + (size_t)(bm + lr) * DDIM + lc;
        const int wr = bn + lr;
        const float* wrow = (wr < 384 ? Wkv + (size_t)wr * DDIM
                                      : Wq + (size_t)(wr - 384) * DDIM) + lc;

        for (int k0 = 0; k0 < DDIM; k0 += 16) {
            if (tid < 256) {
                float4 xv = *(const float4*)(xrow + k0);
                float4 wv = *(const float4*)(wrow + k0);
                G.Xs[lc + 0][lr] = xv.x; G.Xs[lc + 1][lr] = xv.y;
                G.Xs[lc + 2][lr] = xv.z; G.Xs[lc + 3][lr] = xv.w;
                G.Ws[lc + 0][lr] = wv.x; G.Ws[lc + 1][lr] = wv.y;
                G.Ws[lc + 2][lr] = wv.z; G.Ws[lc + 3][lr] = wv.w;
            }
            __syncthreads();
            if (tid < 256) {
#pragma unroll
                for (int kk = 0; kk < 16; kk++) {
                    float4 xr4 = *(const float4*)&G.Xs[kk][ty * 4];
                    float4 wr4 = *(const float4*)&G.Ws[kk][tx * 4];
                    float xa[4] = {xr4.x, xr4.y, xr4.z, xr4.w};
                    float wb[4] = {wr4.x, wr4.y, wr4.z, wr4.w};
#pragma unroll
                    for (int a = 0; a < 4; a++)
#pragma unroll
                        for (int c = 0; c < 4; c++)
                            acc[a][c] = fmaf(xa[a], wb[c], acc[a][c]);
                }
            }
            __syncthreads();
        }
        if (tid < 256) {
#pragma unroll
            for (int a = 0; a < 4; a++) {
                float4 o = {acc[a][0], acc[a][1], acc[a][2], acc[a][3]};
                *(float4*)&g_proj[(size_t)(bm + ty * 4 + a) * NPROJ + bn + tx * 4] = o;
            }
        }
        __syncthreads();
        if (tid == 0) redrel(&g_cnt[rb]);
    }
}

// ===========================================================================
// Variant A — EXACT R8 kernel (proven 3261us). Fallback.
// ===========================================================================
__global__ __launch_bounds__(384, 1) void fusedA(
    const float* __restrict__ X, const float* __restrict__ Wkv,
    const float* __restrict__ Wq, const float* __restrict__ Mi,
    const float* __restrict__ Bg, float* __restrict__ out, int write_M)
{
    __shared__ __align__(16) union { GemmS g; ScanA s; } sm;
    const int tid = threadIdx.x;

    if (blockIdx.x >= NSCAN) { gemm_body(sm.g, tid, (int)blockIdx.x, X, Wkv, Wq); return; }

    const int b = blockIdx.x;
    const int g = tid >> 7, r = tid & 127, i = r >> 1, h = tid & 1;
    const int gm1 = (g + 2) % 3;
    const int wid = tid >> 5, lane = tid & 31;
    ScanA& S = sm.s;

    ull Mr2[16], MTr2[16];
    {
        const float* M0 = Mi + ((size_t)(g * BATCH + b)) * 4096;
#pragma unroll
        for (int j = 0; j < 16; j++) {
            float2 a = *(const float2*)&M0[i * 64 + 32 * h + 2 * j];
            Mr2[j]  = pk2(a.x, a.y);
            MTr2[j] = pk2(M0[(32 * h + 2 * j) * 64 + i],
                          M0[(32 * h + 2 * j + 1) * 64 + i]);
        }
    }
    const float bgm = Bg[gm1 * 64 + i];
    const bool pf = (tid >= 128 && tid < 240);
    const int  pidx = tid - 128;
    const bool knw = (wid >= 8 && wid < 11);
    const int  kw = wid - 8;
    int verified = 0;

    if (pf) {
        while (ldacq(&g_cnt[0]) < 7) __nanosleep(64);
#pragma unroll
        for (int rr = 0; rr < 3; rr++) {
            cp16(smem_u32(&S.raw[rr][pidx * 4]),
                 g_proj + (size_t)(rr * BATCH + b) * NPROJ + pidx * 4);
            cp_commit();
        }
        cp16(smem_u32(&S.raw[3][pidx * 4]),
             g_proj + (size_t)(3 * BATCH + b) * NPROJ + pidx * 4);
        cp_commit();
        cp_wait1();
    }
    __syncthreads();
    if (knw) {
        float a0 = S.raw[0][kw * 128 + lane];
        float a1 = S.raw[0][kw * 128 + 32 + lane];
        float ssq = a0 * a0 + a1 * a1;
#pragma unroll
        for (int o = 16; o; o >>= 1) ssq += __shfl_xor_sync(0xffffffffu, ssq, o);
        float inv = __fdividef(1.0f, sqrtf(ssq) + 1e-6f);
        float k0 = a0 * inv, k1 = a1 * inv;
        S.kn[0][kw][lane]      = k0;
        S.kn[0][kw][lane + 32] = k1;
        S.cgkn[0][kw][4 * (lane >> 1) + 2 + (lane & 1)]        = k0;
        S.cgkn[0][kw][4 * ((lane + 32) >> 1) + 2 + (lane & 1)] = k1;
    }
    __syncthreads();

    for (int t = 0; t < T_STEPS; t++) {
        const int cur = t & 7, b4 = t & 3, b2 = t & 1;
        const int nb4 = (t + 1) & 3;

        ull rp = 0ull, ap = 0ull, cp = 0ull;
        {
            const ulonglong2* kg = (const ulonglong2*)(S.kn[b4][g]   + 32 * h);
            const ulonglong2* km = (const ulonglong2*)(S.kn[b4][gm1] + 32 * h);
#pragma unroll
            for (int j4 = 0; j4 < 8; j4++) {
                ulonglong2 kv  = kg[j4];
                ulonglong2 kmv = km[j4];
                rp = f2fma(Mr2[2 * j4],     kv.x,  rp);
                rp = f2fma(Mr2[2 * j4 + 1], kv.y,  rp);
                ap = f2fma(Mr2[2 * j4],     kmv.x, ap);
                ap = f2fma(Mr2[2 * j4 + 1], kmv.y, ap);
                cp = f2fma(MTr2[2 * j4],     kmv.x, cp);
                cp = f2fma(MTr2[2 * j4 + 1], kmv.y, cp);
            }
        }
        float rlo, rhi, alo, ahi, clo, chi;
        upk2(rp, rlo, rhi); upk2(ap, alo, ahi); upk2(cp, clo, chi);
        float rpart = rlo + rhi, apart = alo + ahi, cpart = clo + chi;
        rpart += __shfl_xor_sync(0xffffffffu, rpart, 1);
        apart += __shfl_xor_sync(0xffffffffu, apart, 1);
        cpart += __shfl_xor_sync(0xffffffffu, cpart, 1);
        const int pi = 4 * (i >> 1);
        if (!h) {
            S.rgdl[b2][gm1][pi + (i & 1)]     = sigm(apart + bgm);
            S.rgdl[b2][g]  [pi + 2 + (i & 1)] = S.raw[cur][g * 128 + 64 + i] - rpart;
        } else {
            S.cgkn[b4][gm1][pi + (i & 1)]     = sigm(cpart + bgm);
        }

        if (knw && t + 1 < T_STEPS) {
            float a0 = S.raw[(t + 1) & 7][kw * 128 + lane];
            float a1 = S.raw[(t + 1) & 7][kw * 128 + 32 + lane];
            float ssq = a0 * a0 + a1 * a1;
#pragma unroll
            for (int o = 16; o; o >>= 1) ssq += __shfl_xor_sync(0xffffffffu, ssq, o);
            float inv = __fdividef(1.0f, sqrtf(ssq) + 1e-6f);
            float k0 = a0 * inv, k1 = a1 * inv;
            S.kn[nb4][kw][lane]      = k0;
            S.kn[nb4][kw][lane + 32] = k1;
            S.cgkn[nb4][kw][4 * (lane >> 1) + 2 + (lane & 1)]        = k0;
            S.cgkn[nb4][kw][4 * ((lane + 32) >> 1) + 2 + (lane & 1)] = k1;
        }

        if (pf) {
            const int t4 = t + 4;
            if (t4 < T_STEPS) {
                const int r4 = t4 * BATCH + b;
                const int rb4 = r4 >> 6;
                if (rb4 > verified) {
                    while (ldacq(&g_cnt[rb4]) < 7) __nanosleep(64);
                    verified = rb4;
                }
                cp16(smem_u32(&S.raw[t4 & 7][pidx * 4]),
                     g_proj + (size_t)r4 * NPROJ + pidx * 4);
            }
            cp_commit();
            cp_wait1();
        }
        __syncthreads();

        const float cg_i = S.cgkn[b4][g][pi + (i & 1)];
        const float kn_i = S.cgkn[b4][g][pi + 2 + (i & 1)];
        const float rg_i = S.rgdl[b2][g][pi + (i & 1)];
        const float d_i  = S.rgdl[b2][g][pi + 2 + (i & 1)];
        const ull rgd = pk2(rg_i, rg_i), cgd = pk2(cg_i, cg_i);
        const ull dd  = pk2(d_i,  d_i),  knd = pk2(kn_i, kn_i);
        {
            const ulonglong2* ck = (const ulonglong2*)(S.cgkn[b4][g] + 64 * h);
            const ulonglong2* rd = (const ulonglong2*)(S.rgdl[b2][g] + 64 * h);
#pragma unroll
            for (int j = 0; j < 16; j++) {
                ulonglong2 a  = ck[j];
                ulonglong2 bq = rd[j];
                Mr2[j]  = f2fma(f2mul(Mr2[j],  a.x),  rgd, f2mul(a.y,  dd));
                MTr2[j] = f2fma(f2mul(MTr2[j], bq.x), cgd, f2mul(bq.y, knd));
            }
        }
        if (!g) {
            ull sq = 0ull;
            const ulonglong2* q2 = (const ulonglong2*)(S.raw[cur] + 384 + 32 * h);
#pragma unroll
            for (int j4 = 0; j4 < 8; j4++) {
                ulonglong2 q = q2[j4];
                sq = f2fma(Mr2[2 * j4],     q.x, sq);
                sq = f2fma(Mr2[2 * j4 + 1], q.y, sq);
            }
            float slo, shi; upk2(sq, slo, shi);
            float s = slo + shi;
            s += __shfl_xor_sync(0xffffffffu, s, 1);
            if (!h) out[((size_t)t * BATCH + b) * 64 + i] = s * sigm(s);
        }
    }

    if (write_M) {
        float* Mo = out + NOUT + ((size_t)(g * BATCH + b)) * 4096
                    + (size_t)i * 64 + 32 * h;
#pragma unroll
        for (int j = 0; j < 16; j++) {
            float a, c; upk2(Mr2[j], a, c);
            Mo[2 * j] = a; Mo[2 * j + 1] = c;
        }
    }
}

// ===========================================================================
// Variant B — kn kept in registers across the barrier; plain cg array
// (region B: 8 LDS.128 fewer); prefetch issued before dots. Guarded by regs.
// ===========================================================================
__global__ __launch_bounds__(384, 1) void fusedB(
    const float* __restrict__ X, const float* __restrict__ Wkv,
    const float* __restrict__ Wq, const float* __restrict__ Mi,
    const float* __restrict__ Bg, float* __restrict__ out, int write_M)
{
    __shared__ __align__(16) union { GemmS g; ScanB s; } sm;
    const int tid = threadIdx.x;

    if (blockIdx.x >= NSCAN) { gemm_body(sm.g, tid, (int)blockIdx.x, X, Wkv, Wq); return; }

    const int b = blockIdx.x;
    const int g = tid >> 7, r = tid & 127, i = r >> 1, h = tid & 1;
    const int gm1 = (g + 2) % 3;
    const int wid = tid >> 5, lane = tid & 31;
    ScanB& S = sm.s;

    ull Mr2[16], MTr2[16];
    {
        const float* M0 = Mi + ((size_t)(g * BATCH + b)) * 4096;
#pragma unroll
        for (int j = 0; j < 16; j++) {
            float2 a = *(const float2*)&M0[i * 64 + 32 * h + 2 * j];
            Mr2[j]  = pk2(a.x, a.y);
            MTr2[j] = pk2(M0[(32 * h + 2 * j) * 64 + i],
                          M0[(32 * h + 2 * j + 1) * 64 + i]);
        }
    }
    const float bgm = Bg[gm1 * 64 + i];
    const bool pf = (tid >= 128 && tid < 240);
    const int  pidx = tid - 128;
    const bool knw = (wid >= 8 && wid < 11);
    const int  kw = wid - 8;
    int verified = 0;

    if (pf) {
        while (ldacq(&g_cnt[0]) < 7) __nanosleep(64);
#pragma unroll
        for (int rr = 0; rr < 3; rr++) {
            cp16(smem_u32(&S.raw[rr][pidx * 4]),
                 g_proj + (size_t)(rr * BATCH + b) * NPROJ + pidx * 4);
            cp_commit();
        }
        cp16(smem_u32(&S.raw[3][pidx * 4]),
             g_proj + (size_t)(3 * BATCH + b) * NPROJ + pidx * 4);
        cp_commit();
        cp_wait1();
    }
    __syncthreads();
    if (knw) {         // kn for row 0 (plain array only)
        float a0 = S.raw[0][kw * 128 + lane];
        float a1 = S.raw[0][kw * 128 + 32 + lane];
        float ssq = a0 * a0 + a1 * a1;
#pragma unroll
        for (int o = 16; o; o >>= 1) ssq += __shfl_xor_sync(0xffffffffu, ssq, o);
        float inv = __fdividef(1.0f, sqrtf(ssq) + 1e-6f);
        S.kn[0][kw][lane]      = a0 * inv;
        S.kn[0][kw][lane + 32] = a1 * inv;
    }
    __syncthreads();

    for (int t = 0; t < T_STEPS; t++) {
        const int cur = t & 7, b4 = t & 3, b2 = t & 1;
        const int nb4 = (t + 1) & 3;

        // ---- prefetch FIRST (LDG in flight during dots) ----
        if (pf) {
            const int t4 = t + 4;
            if (t4 < T_STEPS) {
                const int r4 = t4 * BATCH + b;
                const int rb4 = r4 >> 6;
                if (rb4 > verified) {
                    while (ldacq(&g_cnt[rb4]) < 7) __nanosleep(64);
                    verified = rb4;
                }
                cp16(smem_u32(&S.raw[t4 & 7][pidx * 4]),
                     g_proj + (size_t)r4 * NPROJ + pidx * 4);
            }
            cp_commit();
        }

        // ---- dots; kn pairs of own group stay in kgr[] across the barrier
        ull kgr[16];
        ull rp = 0ull, ap = 0ull, cp = 0ull;
        {
            const ulonglong2* kg = (const ulonglong2*)(S.kn[b4][g]   + 32 * h);
            const ulonglong2* km = (const ulonglong2*)(S.kn[b4][gm1] + 32 * h);
#pragma unroll
            for (int j4 = 0; j4 < 8; j4++) {
                ulonglong2 kv  = kg[j4];
                ulonglong2 kmv = km[j4];
                kgr[2 * j4] = kv.x; kgr[2 * j4 + 1] = kv.y;
                rp = f2fma(Mr2[2 * j4],     kv.x,  rp);
                rp = f2fma(Mr2[2 * j4 + 1], kv.y,  rp);
                ap = f2fma(Mr2[2 * j4],     kmv.x, ap);
                ap = f2fma(Mr2[2 * j4 + 1], kmv.y, ap);
                cp = f2fma(MTr2[2 * j4],     kmv.x, cp);
                cp = f2fma(MTr2[2 * j4 + 1], kmv.y, cp);
            }
        }
        float rlo, rhi, alo, ahi, clo, chi;
        upk2(rp, rlo, rhi); upk2(ap, alo, ahi); upk2(cp, clo, chi);
        float rpart = rlo + rhi, apart = alo + ahi, cpart = clo + chi;
        rpart += __shfl_xor_sync(0xffffffffu, rpart, 1);
        apart += __shfl_xor_sync(0xffffffffu, apart, 1);
        cpart += __shfl_xor_sync(0xffffffffu, cpart, 1);
        const int pi = 4 * (i >> 1);
        if (!h) {
            S.rgdl[b2][gm1][pi + (i & 1)]     = sigm(apart + bgm);
            S.rgdl[b2][g]  [pi + 2 + (i & 1)] = S.raw[cur][g * 128 + 64 + i] - rpart;
        } else {
            S.cg[b4][gm1][i]                  = sigm(cpart + bgm);
        }

        // ---- kn for row t+1 (warps 8-10, plain array only) ----
        if (knw && t + 1 < T_STEPS) {
            float a0 = S.raw[(t + 1) & 7][kw * 128 + lane];
            float a1 = S.raw[(t + 1) & 7][kw * 128 + 32 + lane];
            float ssq = a0 * a0 + a1 * a1;
#pragma unroll
            for (int o = 16; o; o >>= 1) ssq += __shfl_xor_sync(0xffffffffu, ssq, o);
            float inv = __fdividef(1.0f, sqrtf(ssq) + 1e-6f);
            S.kn[nb4][kw][lane]      = a0 * inv;
            S.kn[nb4][kw][lane + 32] = a1 * inv;
        }

        if (pf) cp_wait1();
        __syncthreads();

        // ---- region B: update (cg plain loads + kn from regs) + output ----
        const float cg_i = S.cg[b4][g][i];
        const float kn_i = S.kn[b4][g][i];
        const float rg_i = S.rgdl[b2][g][pi + (i & 1)];
        const float d_i  = S.rgdl[b2][g][pi + 2 + (i & 1)];
        const ull rgd = pk2(rg_i, rg_i), cgd = pk2(cg_i, cg_i);
        const ull dd  = pk2(d_i,  d_i),  knd = pk2(kn_i, kn_i);
        {
            const ulonglong2* cgp = (const ulonglong2*)(S.cg[b4][g] + 32 * h);
            const ulonglong2* rd  = (const ulonglong2*)(S.rgdl[b2][g] + 64 * h);
#pragma unroll
            for (int j4 = 0; j4 < 8; j4++) {
                ulonglong2 cgv = cgp[j4];          // {cg pair 2j4, cg pair 2j4+1}
                ulonglong2 bq0 = rd[2 * j4];       // {rg pair, dl pair}
                ulonglong2 bq1 = rd[2 * j4 + 1];
                Mr2[2*j4]   = f2fma(f2mul(Mr2[2*j4],   cgv.x), rgd,
                                    f2mul(kgr[2*j4],   dd));
                Mr2[2*j4+1] = f2fma(f2mul(Mr2[2*j4+1], cgv.y), rgd,
                                    f2mul(kgr[2*j4+1], dd));
                MTr2[2*j4]   = f2fma(f2mul(MTr2[2*j4],   bq0.x), cgd,
                                     f2mul(bq0.y, knd));
                MTr2[2*j4+1] = f2fma(f2mul(MTr2[2*j4+1], bq1.x), cgd,
                                     f2mul(bq1.y, knd));
            }
        }
        if (!g) {
            ull sq = 0ull;
            const ulonglong2* q2 = (const ulonglong2*)(S.raw[cur] + 384 + 32 * h);
#pragma unroll
            for (int j4 = 0; j4 < 8; j4++) {
                ulonglong2 q = q2[j4];
                sq = f2fma(Mr2[2 * j4],     q.x, sq);
                sq = f2fma(Mr2[2 * j4 + 1], q.y, sq);
            }
            float slo, shi; upk2(sq, slo, shi);
            float s = slo + shi;
            s += __shfl_xor_sync(0xffffffffu, s, 1);
            if (!h) out[((size_t)t * BATCH + b) * 64 + i] = s * sigm(s);
        }
    }

    if (write_M) {
        float* Mo = out + NOUT + ((size_t)(g * BATCH + b)) * 4096
                    + (size_t)i * 64 + 32 * h;
#pragma unroll
        for (int j = 0; j < 16; j++) {
            float a, c; upk2(Mr2[j], a, c);
            Mo[2 * j] = a; Mo[2 * j + 1] = c;
        }
    }
}

// ---------------------------------------------------------------------------
extern "C" void kernel_launch(void* const* d_in, const int* in_sizes, int n_in,
                              void* d_out, int out_size)
{
    const float *x = nullptr, *Mi = nullptr, *Wkv = nullptr,
                *Wq = nullptr, *Bg = nullptr;
    for (int idx = 0; idx < n_in; idx++) {
        switch (in_sizes[idx]) {
            case 33554432: x   = (const float*)d_in[idx]; break;
            case 196608:   Mi  = (const float*)d_in[idx]; break;
            case 393216:   Wkv = (const float*)d_in[idx]; break;
            case 65536:    Wq  = (const float*)d_in[idx]; break;
            case 192:      Bg  = (const float*)d_in[idx]; break;
        }
    }
    if (!x || !Mi || !Wkv || !Wq || !Bg) {
        x   = (const float*)d_in[0];
        Mi  = (const float*)d_in[1];
        Wkv = (const float*)d_in[2];
        Wq  = (const float*)d_in[3];
        Bg  = (const float*)d_in[4];
    }

    const int write_M = (out_size >= NOUT + MSIZE) ? 1 : 0;

    // Guard: variant B only with clear register headroom (no spill, below the
    // 170-reg cap with margin — avoids the at-cap codegen cliff seen in R7).
    cudaFuncAttributes attr;
    bool useB = false;
    if (cudaFuncGetAttributes(&attr, (const void*)fusedB) == cudaSuccess)
        useB = (attr.localSizeBytes == 0 && attr.numRegs > 0 &&
                attr.numRegs <= 168);

    zero_cnt<<<1, 512>>>();
    if (useB)
        fusedB<<<NCTA, 384>>>(x, Wkv, Wq, Mi, Bg, (float*)d_out, write_M);
    else
        fusedA<<<NCTA, 384>>>(x, Wkv, Wq, Mi, Bg, (float*)d_out, write_M);
}

// round 11
// speedup vs baseline: 1.1526x; 1.0369x over previous
#include <cuda_runtime.h>
#include <math.h>

#define T_STEPS 2048
#define BATCH   16
#define DDIM    1024
#define NPROJ   448           // 384 (kv) + 64 (q)
#define NOUT    (T_STEPS*BATCH*64)
#define MSIZE   (3*BATCH*64*64)
#define NSCAN   16
#define NCTA    148
#define NGEMM   (NCTA-NSCAN)
#define NRB     512           // row blocks of 64 proj rows (= 4 timesteps)
#define NTILES  (NRB*7)

__device__ float g_proj[(size_t)T_STEPS * BATCH * NPROJ];
__device__ float g_ssq[(size_t)T_STEPS * BATCH * 4];   // per-row k ssq (3 used, 16B stride)
__device__ int   g_cnt[NRB];

typedef unsigned long long ull;

__device__ __forceinline__ ull pk2(float lo, float hi) {
    ull r; asm("mov.b64 %0,{%1,%2};" : "=l"(r) : "f"(lo), "f"(hi)); return r;
}
__device__ __forceinline__ void upk2(ull v, float& a, float& b) {
    asm("mov.b64 {%0,%1},%2;" : "=f"(a), "=f"(b) : "l"(v));
}
__device__ __forceinline__ ull f2fma(ull a, ull b, ull c) {
    ull d; asm("fma.rn.f32x2 %0,%1,%2,%3;" : "=l"(d) : "l"(a), "l"(b), "l"(c)); return d;
}
__device__ __forceinline__ ull f2mul(ull a, ull b) {
    ull d; asm("mul.rn.f32x2 %0,%1,%2;" : "=l"(d) : "l"(a), "l"(b)); return d;
}
__device__ __forceinline__ int ldacq(const int* p) {
    int v; asm volatile("ld.acquire.gpu.global.b32 %0,[%1];" : "=r"(v) : "l"(p) : "memory"); return v;
}
__device__ __forceinline__ void redrel(int* p) {
    asm volatile("red.release.gpu.global.add.s32 [%0],1;" :: "l"(p) : "memory");
}
__device__ __forceinline__ unsigned smem_u32(const void* p) {
    unsigned a;
    asm("{.reg .u64 t; cvta.to.shared.u64 t,%1; cvt.u32.u64 %0,t;}" : "=r"(a) : "l"(p));
    return a;
}
__device__ __forceinline__ void cp16(unsigned dst, const void* src) {
    asm volatile("cp.async.cg.shared.global [%0],[%1],16;" :: "r"(dst), "l"(src) : "memory");
}
__device__ __forceinline__ void cp_commit() {
    asm volatile("cp.async.commit_group;" ::: "memory");
}
__device__ __forceinline__ void cp_wait1() {
    asm volatile("cp.async.wait_group 1;" ::: "memory");
}
__device__ __forceinline__ float sigm(float x) {
    return __fdividef(1.0f, 1.0f + __expf(-x));
}

__global__ void zero_cnt() { if (threadIdx.x < NRB) g_cnt[threadIdx.x] = 0; }

struct GemmS { float Xs[16][64]; float Ws[16][64]; };
struct ScanB {                 // R10 layout
    float raw[8][NPROJ];
    float kn[4][3][64];
    float cg[4][3][64];
    float rgdl[2][3][128];     // {rg[2p],rg[2p+1],dl[2p],dl[2p+1]}
};
struct ScanC {                 // + ssq ring
    float raw[8][NPROJ];
    float kn[4][3][64];
    float cg[4][3][64];
    float rgdl[2][3][128];
    float ssq[8][4];
};

// ===========================================================================
// GEMM producer body. Also emits per-row k-group sum-of-squares (cb 0/2/4)
// so the scan need not reduce norms (hidden cost on 132 SMs).
// ===========================================================================
__device__ __forceinline__ void gemm_body(
    GemmS& G, int tid, int bx,
    const float* __restrict__ X, const float* __restrict__ Wkv,
    const float* __restrict__ Wq)
{
    const int tx = tid & 15;
    const int ty = tid >> 4;
    const int lr = tid >> 2;
    const int lc = (tid & 3) * 4;

    for (int tt = bx - NSCAN; tt < NTILES; tt += NGEMM) {
        const int rb = tt / 7, cb = tt % 7;
        const int bm = rb * 64, bn = cb * 64;

        float acc[4][4];
#pragma unroll
        for (int a = 0; a < 4; a++)
#pragma unroll
            for (int c = 0; c < 4; c++) acc[a][c] = 0.f;

        const float* xrow = X + (size_t)(bm + lr) * DDIM + lc;
        const int wr = bn + lr;
        const float* wrow = (wr < 384 ? Wkv + (size_t)wr * DDIM
                                      : Wq + (size_t)(wr - 384) * DDIM) + lc;

        for (int k0 = 0; k0 < DDIM; k0 += 16) {
            if (tid < 256) {
                float4 xv = *(const float4*)(xrow + k0);
                float4 wv = *(const float4*)(wrow + k0);
                G.Xs[lc + 0][lr] = xv.x; G.Xs[lc + 1][lr] = xv.y;
                G.Xs[lc + 2][lr] = xv.z; G.Xs[lc + 3][lr] = xv.w;
                G.Ws[lc + 0][lr] = wv.x; G.Ws[lc + 1][lr] = wv.y;
                G.Ws[lc + 2][lr] = wv.z; G.Ws[lc + 3][lr] = wv.w;
            }
            __syncthreads();
            if (tid < 256) {
#pragma unroll
                for (int kk = 0; kk < 16; kk++) {
                    float4 xr4 = *(const float4*)&G.Xs[kk][ty * 4];
                    float4 wr4 = *(const float4*)&G.Ws[kk][tx * 4];
                    float xa[4] = {xr4.x, xr4.y, xr4.z, xr4.w};
                    float wb[4] = {wr4.x, wr4.y, wr4.z, wr4.w};
#pragma unroll
                    for (int a = 0; a < 4; a++)
#pragma unroll
                        for (int c = 0; c < 4; c++)
                            acc[a][c] = fmaf(xa[a], wb[c], acc[a][c]);
                }
            }
            __syncthreads();
        }
        if (tid < 256) {
#pragma unroll
            for (int a = 0; a < 4; a++) {
                float4 o = {acc[a][0], acc[a][1], acc[a][2], acc[a][3]};
                *(float4*)&g_proj[(size_t)(bm + ty * 4 + a) * NPROJ + bn + tx * 4] = o;
            }
            // k-tiles (cb 0/2/4): row sum-of-squares, reduce over tx lanes
            if ((cb & 1) == 0 && cb < 6) {
                const int grp = cb >> 1;
                float p[4];
#pragma unroll
                for (int a = 0; a < 4; a++)
                    p[a] = acc[a][0]*acc[a][0] + acc[a][1]*acc[a][1]
                         + acc[a][2]*acc[a][2] + acc[a][3]*acc[a][3];
#pragma unroll
                for (int o = 1; o < 16; o <<= 1) {
#pragma unroll
                    for (int a = 0; a < 4; a++)
                        p[a] += __shfl_xor_sync(0xffffffffu, p[a], o);
                }
                if (tx == 0) {
#pragma unroll
                    for (int a = 0; a < 4; a++)
                        g_ssq[(size_t)(bm + ty * 4 + a) * 4 + grp] = p[a];
                }
            }
        }
        __syncthreads();
        if (tid == 0) redrel(&g_cnt[rb]);
    }
}

// ===========================================================================
// Variant C — NEW: kn-next uses producer-computed ssq (no 5-shfl reduce on
// the barrier-critical leg). Otherwise identical to the proven R10 kernel.
// ===========================================================================
__global__ __launch_bounds__(384, 1) void fusedC(
    const float* __restrict__ X, const float* __restrict__ Wkv,
    const float* __restrict__ Wq, const float* __restrict__ Mi,
    const float* __restrict__ Bg, float* __restrict__ out, int write_M)
{
    __shared__ __align__(16) union { GemmS g; ScanC s; } sm;
    const int tid = threadIdx.x;

    if (blockIdx.x >= NSCAN) { gemm_body(sm.g, tid, (int)blockIdx.x, X, Wkv, Wq); return; }

    const int b = blockIdx.x;
    const int g = tid >> 7, r = tid & 127, i = r >> 1, h = tid & 1;
    const int gm1 = (g + 2) % 3;
    const int wid = tid >> 5, lane = tid & 31;
    ScanC& S = sm.s;

    ull Mr2[16], MTr2[16];
    {
        const float* M0 = Mi + ((size_t)(g * BATCH + b)) * 4096;
#pragma unroll
        for (int j = 0; j < 16; j++) {
            float2 a = *(const float2*)&M0[i * 64 + 32 * h + 2 * j];
            Mr2[j]  = pk2(a.x, a.y);
            MTr2[j] = pk2(M0[(32 * h + 2 * j) * 64 + i],
                          M0[(32 * h + 2 * j + 1) * 64 + i]);
        }
    }
    const float bgm = Bg[gm1 * 64 + i];
    const bool pf = (tid >= 128 && tid < 240);
    const int  pidx = tid - 128;
    const bool knw = (wid >= 8 && wid < 11);
    const int  kw = wid - 8;
    int verified = 0;

    if (pf) {
        while (ldacq(&g_cnt[0]) < 7) __nanosleep(64);
#pragma unroll
        for (int rr = 0; rr < 3; rr++) {
            cp16(smem_u32(&S.raw[rr][pidx * 4]),
                 g_proj + (size_t)(rr * BATCH + b) * NPROJ + pidx * 4);
            if (pidx == 0)
                cp16(smem_u32(&S.ssq[rr][0]),
                     g_ssq + (size_t)(rr * BATCH + b) * 4);
            cp_commit();
        }
        cp16(smem_u32(&S.raw[3][pidx * 4]),
             g_proj + (size_t)(3 * BATCH + b) * NPROJ + pidx * 4);
        if (pidx == 0)
            cp16(smem_u32(&S.ssq[3][0]),
                 g_ssq + (size_t)(3 * BATCH + b) * 4);
        cp_commit();
        cp_wait1();    // rows 0..2 (+ssq) complete, row 3 pending
    }
    __syncthreads();
    if (knw) {         // kn for row 0 via staged ssq (no reduce)
        float inv = __fdividef(1.0f, sqrtf(S.ssq[0][kw]) + 1e-6f);
        float a0 = S.raw[0][kw * 128 + lane];
        float a1 = S.raw[0][kw * 128 + 32 + lane];
        S.kn[0][kw][lane]      = a0 * inv;
        S.kn[0][kw][lane + 32] = a1 * inv;
    }
    __syncthreads();

    for (int t = 0; t < T_STEPS; t++) {
        const int cur = t & 7, b4 = t & 3, b2 = t & 1;
        const int nb4 = (t + 1) & 3;

        // ---- prefetch FIRST (LDG in flight during dots) ----
        if (pf) {
            const int t4 = t + 4;
            if (t4 < T_STEPS) {
                const int r4 = t4 * BATCH + b;
                const int rb4 = r4 >> 6;
                if (rb4 > verified) {
                    while (ldacq(&g_cnt[rb4]) < 7) __nanosleep(64);
                    verified = rb4;
                }
                cp16(smem_u32(&S.raw[t4 & 7][pidx * 4]),
                     g_proj + (size_t)r4 * NPROJ + pidx * 4);
                if (pidx == 0)
                    cp16(smem_u32(&S.ssq[t4 & 7][0]),
                         g_ssq + (size_t)r4 * 4);
            }
            cp_commit();
        }

        // ---- dots; own-group kn pairs stay in regs across the barrier ----
        ull kgr[16];
        ull rp = 0ull, ap = 0ull, cp = 0ull;
        {
            const ulonglong2* kg = (const ulonglong2*)(S.kn[b4][g]   + 32 * h);
            const ulonglong2* km = (const ulonglong2*)(S.kn[b4][gm1] + 32 * h);
#pragma unroll
            for (int j4 = 0; j4 < 8; j4++) {
                ulonglong2 kv  = kg[j4];
                ulonglong2 kmv = km[j4];
                kgr[2 * j4] = kv.x; kgr[2 * j4 + 1] = kv.y;
                rp = f2fma(Mr2[2 * j4],     kv.x,  rp);
                rp = f2fma(Mr2[2 * j4 + 1], kv.y,  rp);
                ap = f2fma(Mr2[2 * j4],     kmv.x, ap);
                ap = f2fma(Mr2[2 * j4 + 1], kmv.y, ap);
                cp = f2fma(MTr2[2 * j4],     kmv.x, cp);
                cp = f2fma(MTr2[2 * j4 + 1], kmv.y, cp);
            }
        }
        float rlo, rhi, alo, ahi, clo, chi;
        upk2(rp, rlo, rhi); upk2(ap, alo, ahi); upk2(cp, clo, chi);
        float rpart = rlo + rhi, apart = alo + ahi, cpart = clo + chi;
        rpart += __shfl_xor_sync(0xffffffffu, rpart, 1);
        apart += __shfl_xor_sync(0xffffffffu, apart, 1);
        cpart += __shfl_xor_sync(0xffffffffu, cpart, 1);
        const int pi = 4 * (i >> 1);
        if (!h) {
            S.rgdl[b2][gm1][pi + (i & 1)]     = sigm(apart + bgm);
            S.rgdl[b2][g]  [pi + 2 + (i & 1)] = S.raw[cur][g * 128 + 64 + i] - rpart;
        } else {
            S.cg[b4][gm1][i]                  = sigm(cpart + bgm);
        }

        // ---- kn for row t+1 (warps 8-10; ssq staged — no reduction) ----
        if (knw && t + 1 < T_STEPS) {
            float inv = __fdividef(1.0f, sqrtf(S.ssq[(t + 1) & 7][kw]) + 1e-6f);
            float a0 = S.raw[(t + 1) & 7][kw * 128 + lane];
            float a1 = S.raw[(t + 1) & 7][kw * 128 + 32 + lane];
            S.kn[nb4][kw][lane]      = a0 * inv;
            S.kn[nb4][kw][lane + 32] = a1 * inv;
        }

        if (pf) cp_wait1();
        __syncthreads();

        // ---- region B: update (cg plain loads + kn from regs) + output ----
        const float cg_i = S.cg[b4][g][i];
        const float kn_i = S.kn[b4][g][i];
        const float rg_i = S.rgdl[b2][g][pi + (i & 1)];
        const float d_i  = S.rgdl[b2][g][pi + 2 + (i & 1)];
        const ull rgd = pk2(rg_i, rg_i), cgd = pk2(cg_i, cg_i);
        const ull dd  = pk2(d_i,  d_i),  knd = pk2(kn_i, kn_i);
        {
            const ulonglong2* cgp = (const ulonglong2*)(S.cg[b4][g] + 32 * h);
            const ulonglong2* rd  = (const ulonglong2*)(S.rgdl[b2][g] + 64 * h);
#pragma unroll
            for (int j4 = 0; j4 < 8; j4++) {
                ulonglong2 cgv = cgp[j4];
                ulonglong2 bq0 = rd[2 * j4];
                ulonglong2 bq1 = rd[2 * j4 + 1];
                Mr2[2*j4]   = f2fma(f2mul(Mr2[2*j4],   cgv.x), rgd,
                                    f2mul(kgr[2*j4],   dd));
                Mr2[2*j4+1] = f2fma(f2mul(Mr2[2*j4+1], cgv.y), rgd,
                                    f2mul(kgr[2*j4+1], dd));
                MTr2[2*j4]   = f2fma(f2mul(MTr2[2*j4],   bq0.x), cgd,
                                     f2mul(bq0.y, knd));
                MTr2[2*j4+1] = f2fma(f2mul(MTr2[2*j4+1], bq1.x), cgd,
                                     f2mul(bq1.y, knd));
            }
        }
        if (!g) {
            ull sq = 0ull;
            const ulonglong2* q2 = (const ulonglong2*)(S.raw[cur] + 384 + 32 * h);
#pragma unroll
            for (int j4 = 0; j4 < 8; j4++) {
                ulonglong2 q = q2[j4];
                sq = f2fma(Mr2[2 * j4],     q.x, sq);
                sq = f2fma(Mr2[2 * j4 + 1], q.y, sq);
            }
            float slo, shi; upk2(sq, slo, shi);
            float s = slo + shi;
            s += __shfl_xor_sync(0xffffffffu, s, 1);
            if (!h) out[((size_t)t * BATCH + b) * 64 + i] = s * sigm(s);
        }
    }

    if (write_M) {
        float* Mo = out + NOUT + ((size_t)(g * BATCH + b)) * 4096
                    + (size_t)i * 64 + 32 * h;
#pragma unroll
        for (int j = 0; j < 16; j++) {
            float a, c; upk2(Mr2[j], a, c);
            Mo[2 * j] = a; Mo[2 * j + 1] = c;
        }
    }
}

// ===========================================================================
// Variant B — EXACT R10 kernel (proven 2995us). Fallback.
// ===========================================================================
__global__ __launch_bounds__(384, 1) void fusedB(
    const float* __restrict__ X, const float* __restrict__ Wkv,
    const float* __restrict__ Wq, const float* __restrict__ Mi,
    const float* __restrict__ Bg, float* __restrict__ out, int write_M)
{
    __shared__ __align__(16) union { GemmS g; ScanB s; } sm;
    const int tid = threadIdx.x;

    if (blockIdx.x >= NSCAN) { gemm_body(sm.g, tid, (int)blockIdx.x, X, Wkv, Wq); return; }

    const int b = blockIdx.x;
    const int g = tid >> 7, r = tid & 127, i = r >> 1, h = tid & 1;
    const int gm1 = (g + 2) % 3;
    const int wid = tid >> 5, lane = tid & 31;
    ScanB& S = sm.s;

    ull Mr2[16], MTr2[16];
    {
        const float* M0 = Mi + ((size_t)(g * BATCH + b)) * 4096;
#pragma unroll
        for (int j = 0; j < 16; j++) {
            float2 a = *(const float2*)&M0[i * 64 + 32 * h + 2 * j];
            Mr2[j]  = pk2(a.x, a.y);
            MTr2[j] = pk2(M0[(32 * h + 2 * j) * 64 + i],
                          M0[(32 * h + 2 * j + 1) * 64 + i]);
        }
    }
    const float bgm = Bg[gm1 * 64 + i];
    const bool pf = (tid >= 128 && tid < 240);
    const int  pidx = tid - 128;
    const bool knw = (wid >= 8 && wid < 11);
    const int  kw = wid - 8;
    int verified = 0;

    if (pf) {
        while (ldacq(&g_cnt[0]) < 7) __nanosleep(64);
#pragma unroll
        for (int rr = 0; rr < 3; rr++) {
            cp16(smem_u32(&S.raw[rr][pidx * 4]),
                 g_proj + (size_t)(rr * BATCH + b) * NPROJ + pidx * 4);
            cp_commit();
        }
        cp16(smem_u32(&S.raw[3][pidx * 4]),
             g_proj + (size_t)(3 * BATCH + b) * NPROJ + pidx * 4);
        cp_commit();
        cp_wait1();
    }
    __syncthreads();
    if (knw) {
        float a0 = S.raw[0][kw * 128 + lane];
        float a1 = S.raw[0][kw * 128 + 32 + lane];
        float ssq = a0 * a0 + a1 * a1;
#pragma unroll
        for (int o = 16; o; o >>= 1) ssq += __shfl_xor_sync(0xffffffffu, ssq, o);
        float inv = __fdividef(1.0f, sqrtf(ssq) + 1e-6f);
        S.kn[0][kw][lane]      = a0 * inv;
        S.kn[0][kw][lane + 32] = a1 * inv;
    }
    __syncthreads();

    for (int t = 0; t < T_STEPS; t++) {
        const int cur = t & 7, b4 = t & 3, b2 = t & 1;
        const int nb4 = (t + 1) & 3;

        if (pf) {
            const int t4 = t + 4;
            if (t4 < T_STEPS) {
                const int r4 = t4 * BATCH + b;
                const int rb4 = r4 >> 6;
                if (rb4 > verified) {
                    while (ldacq(&g_cnt[rb4]) < 7) __nanosleep(64);
                    verified = rb4;
                }
                cp16(smem_u32(&S.raw[t4 & 7][pidx * 4]),
                     g_proj + (size_t)r4 * NPROJ + pidx * 4);
            }
            cp_commit();
        }

        ull kgr[16];
        ull rp = 0ull, ap = 0ull, cp = 0ull;
        {
            const ulonglong2* kg = (const ulonglong2*)(S.kn[b4][g]   + 32 * h);
            const ulonglong2* km = (const ulonglong2*)(S.kn[b4][gm1] + 32 * h);
#pragma unroll
            for (int j4 = 0; j4 < 8; j4++) {
                ulonglong2 kv  = kg[j4];
                ulonglong2 kmv = km[j4];
                kgr[2 * j4] = kv.x; kgr[2 * j4 + 1] = kv.y;
                rp = f2fma(Mr2[2 * j4],     kv.x,  rp);
                rp = f2fma(Mr2[2 * j4 + 1], kv.y,  rp);
                ap = f2fma(Mr2[2 * j4],     kmv.x, ap);
                ap = f2fma(Mr2[2 * j4 + 1], kmv.y, ap);
                cp = f2fma(MTr2[2 * j4],     kmv.x, cp);
                cp = f2fma(MTr2[2 * j4 + 1], kmv.y, cp);
            }
        }
        float rlo, rhi, alo, ahi, clo, chi;
        upk2(rp, rlo, rhi); upk2(ap, alo, ahi); upk2(cp, clo, chi);
        float rpart = rlo + rhi, apart = alo + ahi, cpart = clo + chi;
        rpart += __shfl_xor_sync(0xffffffffu, rpart, 1);
        apart += __shfl_xor_sync(0xffffffffu, apart, 1);
        cpart += __shfl_xor_sync(0xffffffffu, cpart, 1);
        const int pi = 4 * (i >> 1);
        if (!h) {
            S.rgdl[b2][gm1][pi + (i & 1)]     = sigm(apart + bgm);
            S.rgdl[b2][g]  [pi + 2 + (i & 1)] = S.raw[cur][g * 128 + 64 + i] - rpart;
        } else {
            S.cg[b4][gm1][i]                  = sigm(cpart + bgm);
        }

        if (knw && t + 1 < T_STEPS) {
            float a0 = S.raw[(t + 1) & 7][kw * 128 + lane];
            float a1 = S.raw[(t + 1) & 7][kw * 128 + 32 + lane];
            float ssq = a0 * a0 + a1 * a1;
#pragma unroll
            for (int o = 16; o; o >>= 1) ssq += __shfl_xor_sync(0xffffffffu, ssq, o);
            float inv = __fdividef(1.0f, sqrtf(ssq) + 1e-6f);
            S.kn[nb4][kw][lane]      = a0 * inv;
            S.kn[nb4][kw][lane + 32] = a1 * inv;
        }

        if (pf) cp_wait1();
        __syncthreads();

        const float cg_i = S.cg[b4][g][i];
        const float kn_i = S.kn[b4][g][i];
        const float rg_i = S.rgdl[b2][g][pi + (i & 1)];
        const float d_i  = S.rgdl[b2][g][pi + 2 + (i & 1)];
        const ull rgd = pk2(rg_i, rg_i), cgd = pk2(cg_i, cg_i);
        const ull dd  = pk2(d_i,  d_i),  knd = pk2(kn_i, kn_i);
        {
            const ulonglong2* cgp = (const ulonglong2*)(S.cg[b4][g] + 32 * h);
            const ulonglong2* rd  = (const ulonglong2*)(S.rgdl[b2][g] + 64 * h);
#pragma unroll
            for (int j4 = 0; j4 < 8; j4++) {
                ulonglong2 cgv = cgp[j4];
                ulonglong2 bq0 = rd[2 * j4];
                ulonglong2 bq1 = rd[2 * j4 + 1];
                Mr2[2*j4]   = f2fma(f2mul(Mr2[2*j4],   cgv.x), rgd,
                                    f2mul(kgr[2*j4],   dd));
                Mr2[2*j4+1] = f2fma(f2mul(Mr2[2*j4+1], cgv.y), rgd,
                                    f2mul(kgr[2*j4+1], dd));
                MTr2[2*j4]   = f2fma(f2mul(MTr2[2*j4],   bq0.x), cgd,
                                     f2mul(bq0.y, knd));
                MTr2[2*j4+1] = f2fma(f2mul(MTr2[2*j4+1], bq1.x), cgd,
                                     f2mul(bq1.y, knd));
            }
        }
        if (!g) {
            ull sq = 0ull;
            const ulonglong2* q2 = (const ulonglong2*)(S.raw[cur] + 384 + 32 * h);
#pragma unroll
            for (int j4 = 0; j4 < 8; j4++) {
                ulonglong2 q = q2[j4];
                sq = f2fma(Mr2[2 * j4],     q.x, sq);
                sq = f2fma(Mr2[2 * j4 + 1], q.y, sq);
            }
            float slo, shi; upk2(sq, slo, shi);
            float s = slo + shi;
            s += __shfl_xor_sync(0xffffffffu, s, 1);
            if (!h) out[((size_t)t * BATCH + b) * 64 + i] = s * sigm(s);
        }
    }

    if (write_M) {
        float* Mo = out + NOUT + ((size_t)(g * BATCH + b)) * 4096
                    + (size_t)i * 64 + 32 * h;
#pragma unroll
        for (int j = 0; j < 16; j++) {
            float a, c; upk2(Mr2[j], a, c);
            Mo[2 * j] = a; Mo[2 * j + 1] = c;
        }
    }
}

// ---------------------------------------------------------------------------
extern "C" void kernel_launch(void* const* d_in, const int* in_sizes, int n_in,
                              void* d_out, int out_size)
{
    const float *x = nullptr, *Mi = nullptr, *Wkv = nullptr,
                *Wq = nullptr, *Bg = nullptr;
    for (int idx = 0; idx < n_in; idx++) {
        switch (in_sizes[idx]) {
            case 33554432: x   = (const float*)d_in[idx]; break;
            case 196608:   Mi  = (const float*)d_in[idx]; break;
            case 393216:   Wkv = (const float*)d_in[idx]; break;
            case 65536:    Wq  = (const float*)d_in[idx]; break;
            case 192:      Bg  = (const float*)d_in[idx]; break;
        }
    }
    if (!x || !Mi || !Wkv || !Wq || !Bg) {
        x   = (const float*)d_in[0];
        Mi  = (const float*)d_in[1];
        Wkv = (const float*)d_in[2];
        Wq  = (const float*)d_in[3];
        Bg  = (const float*)d_in[4];
    }

    const int write_M = (out_size >= NOUT + MSIZE) ? 1 : 0;

    // Guard: variant C only with no spill and clear register headroom
    // (at-cap codegen cliff, see R7 post-mortem). Fallback = exact R10.
    cudaFuncAttributes attr;
    bool useC = false;
    if (cudaFuncGetAttributes(&attr, (const void*)fusedC) == cudaSuccess)
        useC = (attr.localSizeBytes == 0 && attr.numRegs > 0 &&
                attr.numRegs <= 168);

    zero_cnt<<<1, 512>>>();
    if (useC)
        fusedC<<<NCTA, 384>>>(x, Wkv, Wq, Mi, Bg, (float*)d_out, write_M);
    else
        fusedB<<<NCTA, 384>>>(x, Wkv, Wq, Mi, Bg, (float*)d_out, write_M);
}